// round 10
// baseline (speedup 1.0000x reference)
#include <cuda_runtime.h>
#include <cuda_fp16.h>
#include <cstdint>

#define QROW 2048
#define KROW 512
#define SEQ  2048
#define QSC  0.12751743f   /* (1/sqrt(128)) * log2(e) */
#define PBIAS 12.0f
#define ONES2 0x3C003C00u  /* half2(1,1) */

/* buffer (R8 layout): K 64 rows x 68w at 0; V 32 tp x 136w at 4352; ones at V cols 128..135 */
#define VOFF_W 4352
#define BUFW   8704
#define QOFF_W 17408        /* Q region: 128 rows x 68w */
#define SMEM_BYTES 104448   /* (17408 + 8704) * 4 */

__device__ __forceinline__ void hmma(float* c, const uint32_t* a, uint32_t b0, uint32_t b1) {
  asm("mma.sync.aligned.m16n8k16.row.col.f32.f16.f16.f32 "
      "{%0,%1,%2,%3}, {%4,%5,%6,%7}, {%8,%9}, {%0,%1,%2,%3};"
      : "+f"(c[0]), "+f"(c[1]), "+f"(c[2]), "+f"(c[3])
      : "r"(a[0]), "r"(a[1]), "r"(a[2]), "r"(a[3]), "r"(b0), "r"(b1));
}
__device__ __forceinline__ uint32_t pkf(float x, float y) {  /* lo=x, hi=y */
  uint32_t r; asm("cvt.rn.f16x2.f32 %0, %2, %1;" : "=r"(r) : "f"(x), "f"(y)); return r;
}
__device__ __forceinline__ float ex2f(float x) {
  float y; asm("ex2.approx.ftz.f32 %0, %1;" : "=f"(y) : "f"(x)); return y;
}

extern __shared__ uint32_t smw[];

/* fill one 64-token K/V buffer with 512 threads (R8 layouts) */
__device__ __forceinline__ void fill_kv(uint32_t* buf, const float* kp,
                                        const float* vp, int t) {
#pragma unroll 2
  for (int it = 0; it < 4; ++it) {
    const int idx = t + 512 * it, n = idx >> 5, d0 = (idx & 31) << 2;
    float4 kf = *(const float4*)(kp + (size_t)n * KROW + d0);
    *(uint2*)(buf + n * 68 + (d0 >> 1)) = make_uint2(pkf(kf.x, kf.y), pkf(kf.z, kf.w));
  }
#pragma unroll 2
  for (int it = 0; it < 2; ++it) {
    const int slot = t + 512 * it, tp = slot >> 5, d0 = (slot & 31) << 2;
    const float* vr = vp + (size_t)(2 * tp) * KROW + d0;
    float4 va = *(const float4*)(vr);
    float4 vb = *(const float4*)(vr + KROW);
    *(uint4*)(buf + VOFF_W + tp * 136 + d0) =
        make_uint4(pkf(va.x, vb.x), pkf(va.y, vb.y), pkf(va.z, vb.z), pkf(va.w, vb.w));
  }
}

__global__ void __launch_bounds__(512, 1)
fa_hmma6_kernel(const float* __restrict__ q, const float* __restrict__ k,
                const float* __restrict__ v, float* __restrict__ out) {
  const int t = threadIdx.x;
  const int w = t >> 5, lane = t & 31;
  const int g = lane >> 2, tt = lane & 3;
  const int wp = w >> 1;          /* warp pair id: q-rows 16*wp.. */
  const int nh = w & 1;           /* kv n-half: columns 32*nh..32*nh+31 */
  const int qt = 15 - (int)blockIdx.x;
  const int h = blockIdx.y, b = blockIdx.z, hk = h >> 2;

  const float* qg = q + (size_t)(b * SEQ + qt * 128) * QROW + h * 128;
  const float* kg = k + (size_t)b * SEQ * KROW + hk * 128;
  const float* vg = v + (size_t)b * SEQ * KROW + hk * 128;

  /* ---- ones pad columns (both buffers), once ---- */
  if (t < 256) {
    const int o1 = VOFF_W + (t >> 3) * 136 + 128 + (t & 7);
    smw[o1] = ONES2;
    smw[BUFW + o1] = ONES2;
  }

  /* ---- stage Q (scaled fp16) into persistent Q region [m][68w] ---- */
#pragma unroll
  for (int it = 0; it < 8; ++it) {
    const int idx = t + 512 * it, m = idx >> 5, d0 = (idx & 31) << 2;
    float4 qv = *(const float4*)(qg + (size_t)m * QROW + d0);
    *(uint2*)(smw + QOFF_W + m * 68 + (d0 >> 1)) =
        make_uint2(pkf(qv.x * QSC, qv.y * QSC), pkf(qv.z * QSC, qv.w * QSC));
  }
  __syncthreads();

  fill_kv(smw, kg, vg, t);   /* prefill buffer 0 */

  float o[16][4];
#pragma unroll
  for (int nt = 0; nt < 16; ++nt)
#pragma unroll
    for (int i = 0; i < 4; ++i) o[nt][i] = 0.0f;
  float lf[4] = {0.f, 0.f, 0.f, 0.f};

  const int r0 = qt * 128 + 16 * wp + g;     /* thread rows r0, r0+8 */
  const int rmax = qt * 128 + 16 * wp + 15;
  const uint32_t* qb = smw + QOFF_W + (16 * wp + g) * 68 + tt;
  const int nkt = 2 * qt + 2;

  for (int kt = 0; kt < nkt; ++kt) {
    __syncthreads();  /* fill(kt) visible; prior reads of that buffer done */
    const uint32_t* bw = smw + (kt & 1) * BUFW;
    const int cbase = kt * 64 + 32 * nh;       /* warp's first kv column */
    const bool active = (cbase <= rmax);

    float s[4][4];
    if (active) {
      /* ---- S(half) = Q K^T - PBIAS ; Q frags from smem per ks ---- */
#pragma unroll
      for (int nt = 0; nt < 4; ++nt)
#pragma unroll
        for (int i = 0; i < 4; ++i) s[nt][i] = -PBIAS;
#pragma unroll
      for (int ks = 0; ks < 8; ++ks) {
        uint32_t qh[4];
        qh[0] = qb[ks * 8];       qh[1] = qb[ks * 8 + 544];
        qh[2] = qb[ks * 8 + 4];   qh[3] = qb[ks * 8 + 548];
#pragma unroll
        for (int nt = 0; nt < 4; ++nt) {
          const int a = (32 * nh + nt * 8 + g) * 68 + ks * 8 + tt;
          hmma(s[nt], qh, bw[a], bw[a + 4]);
        }
      }
    }

    /* ---- prefetch next kv-tile (overlaps softmax + PV) ---- */
    if (kt + 1 < nkt)
      fill_kv(smw + ((kt + 1) & 1) * BUFW,
              kg + (size_t)((kt + 1) * 64) * KROW,
              vg + (size_t)((kt + 1) * 64) * KROW, t);

    if (active) {
      /* ---- causal mask + exp2 ; P packed straight into A-fragments ---- */
      const bool needMask = (cbase + 31 > qt * 128 + 16 * wp);
      uint32_t pp[4][2];
#pragma unroll
      for (int nt = 0; nt < 4; ++nt) {
        if (needMask) {
          const int c = cbase + nt * 8 + 2 * tt;
          if (c > r0)         s[nt][0] = -1e30f;
          if (c + 1 > r0)     s[nt][1] = -1e30f;
          if (c > r0 + 8)     s[nt][2] = -1e30f;
          if (c + 1 > r0 + 8) s[nt][3] = -1e30f;
        }
        pp[nt][0] = pkf(ex2f(s[nt][0]), ex2f(s[nt][1]));  /* row g   */
        pp[nt][1] = pkf(ex2f(s[nt][2]), ex2f(s[nt][3]));  /* row g+8 */
      }

      /* ---- O += P(half) V(half) ; l += P * ones ---- */
#pragma unroll
      for (int ks = 0; ks < 2; ++ks) {
        uint32_t ap[4];
        ap[0] = pp[2 * ks][0];
        ap[1] = pp[2 * ks][1];
        ap[2] = pp[2 * ks + 1][0];
        ap[3] = pp[2 * ks + 1][1];
        const int vrow = VOFF_W + (16 * nh + 8 * ks + tt) * 136;
#pragma unroll
        for (int nt = 0; nt < 16; ++nt) {
          const int vb = vrow + nt * 8 + g;
          hmma(o[nt], ap, bw[vb], bw[vb + 544]);
        }
        const int vbp = vrow + 128 + g;
        hmma(lf, ap, bw[vbp], bw[vbp + 544]);
      }
    }
  }

  /* ---- pair reduction: odd warp stages O,l ; even warp combines + stores ---- */
  __syncthreads();
  float* stg = (float*)smw;              /* 128 rows x 130 floats */
  float* lfs = (float*)smw + 16640;      /* 128 floats */
  if (nh == 1) {
    const int rA = (16 * wp + g) * 130, rB = rA + 8 * 130;
#pragma unroll
    for (int nt = 0; nt < 16; ++nt) {
      const int cc = nt * 8 + 2 * tt;
      stg[rA + cc] = o[nt][0]; stg[rA + cc + 1] = o[nt][1];
      stg[rB + cc] = o[nt][2]; stg[rB + cc + 1] = o[nt][3];
    }
    lfs[16 * wp + g] = lf[0];
    lfs[16 * wp + g + 8] = lf[2];
  }
  __syncthreads();
  if (nh == 0) {
    const int rA = (16 * wp + g) * 130, rB = rA + 8 * 130;
    const float i0 = 1.0f / (lf[0] + lfs[16 * wp + g]);
    const float i1 = 1.0f / (lf[2] + lfs[16 * wp + g + 8]);
    float* og = out + (size_t)(b * SEQ + r0) * QROW + h * 128 + 2 * tt;
#pragma unroll
    for (int nt = 0; nt < 16; ++nt) {
      const int cc = nt * 8 + 2 * tt;
      *(float2*)(og + nt * 8) =
          make_float2((o[nt][0] + stg[rA + cc]) * i0, (o[nt][1] + stg[rA + cc + 1]) * i0);
      *(float2*)(og + 8 * QROW + nt * 8) =
          make_float2((o[nt][2] + stg[rB + cc]) * i1, (o[nt][3] + stg[rB + cc + 1]) * i1);
    }
  }
}

extern "C" void kernel_launch(void* const* d_in, const int* in_sizes, int n_in,
                              void* d_out, int out_size) {
  const float* q = (const float*)d_in[0];
  const float* k = (const float*)d_in[1];
  const float* v = (const float*)d_in[2];
  float* out = (float*)d_out;
  (void)in_sizes; (void)n_in; (void)out_size;
  cudaFuncSetAttribute(fa_hmma6_kernel, cudaFuncAttributeMaxDynamicSharedMemorySize, SMEM_BYTES);
  fa_hmma6_kernel<<<dim3(16, 16, 4), 512, SMEM_BYTES>>>(q, k, v, out);
}

// round 11
// speedup vs baseline: 1.4191x; 1.4191x over previous
#include <cuda_runtime.h>
#include <cuda_fp16.h>
#include <cstdint>

#define QROW 2048
#define KROW 512
#define SEQ  2048
#define QSC  0.12751743f   /* (1/sqrt(128)) * log2(e) */
#define PBIAS 12.0f
#define ONES2 0x3C003C00u  /* half2(1,1) */

/* buffer: K 64 rows x 68w at 0; V 64 rows x 68w at 4352 (words 64..67 = ones) */
#define VOFF_W 4352
#define BUFW   8704
#define SMEM_BYTES 69632

__device__ __forceinline__ void hmma(float* c, const uint32_t* a, uint32_t b0, uint32_t b1) {
  asm("mma.sync.aligned.m16n8k16.row.col.f32.f16.f16.f32 "
      "{%0,%1,%2,%3}, {%4,%5,%6,%7}, {%8,%9}, {%0,%1,%2,%3};"
      : "+f"(c[0]), "+f"(c[1]), "+f"(c[2]), "+f"(c[3])
      : "r"(a[0]), "r"(a[1]), "r"(a[2]), "r"(a[3]), "r"(b0), "r"(b1));
}
__device__ __forceinline__ uint32_t pkf(float x, float y) {  /* lo=x, hi=y */
  uint32_t r; asm("cvt.rn.f16x2.f32 %0, %2, %1;" : "=r"(r) : "f"(x), "f"(y)); return r;
}
__device__ __forceinline__ float ex2f(float x) {
  float y; asm("ex2.approx.ftz.f32 %0, %1;" : "=f"(y) : "f"(x)); return y;
}
__device__ __forceinline__ uint32_t smem_u32(const void* p) {
  uint32_t a;
  asm("{ .reg .u64 t; cvta.to.shared.u64 t, %1; cvt.u32.u64 %0, t; }" : "=r"(a) : "l"(p));
  return a;
}
__device__ __forceinline__ uint4 ldsm4(uint32_t addr) {
  uint4 r;
  asm volatile("ldmatrix.sync.aligned.m8n8.x4.shared.b16 {%0,%1,%2,%3}, [%4];"
               : "=r"(r.x), "=r"(r.y), "=r"(r.z), "=r"(r.w) : "r"(addr));
  return r;
}
__device__ __forceinline__ uint4 ldsm4t(uint32_t addr) {
  uint4 r;
  asm volatile("ldmatrix.sync.aligned.m8n8.x4.trans.shared.b16 {%0,%1,%2,%3}, [%4];"
               : "=r"(r.x), "=r"(r.y), "=r"(r.z), "=r"(r.w) : "r"(addr));
  return r;
}
__device__ __forceinline__ uint2 ldsm2t(uint32_t addr) {
  uint2 r;
  asm volatile("ldmatrix.sync.aligned.m8n8.x2.trans.shared.b16 {%0,%1}, [%2];"
               : "=r"(r.x), "=r"(r.y) : "r"(addr));
  return r;
}

extern __shared__ uint32_t smw[];

/* fill one 64-token K/V buffer; both natural [row][68w] fp16 */
__device__ __forceinline__ void fill_kv(uint32_t* buf, const float* kp,
                                        const float* vp, int t) {
#pragma unroll 4
  for (int it = 0; it < 8; ++it) {
    const int idx = t + 256 * it, n = idx >> 5, d0 = (idx & 31) << 2;
    const size_t goff = (size_t)n * KROW + d0;
    float4 kf = *(const float4*)(kp + goff);
    float4 vf = *(const float4*)(vp + goff);
    *(uint2*)(buf + n * 68 + (d0 >> 1)) = make_uint2(pkf(kf.x, kf.y), pkf(kf.z, kf.w));
    *(uint2*)(buf + VOFF_W + n * 68 + (d0 >> 1)) = make_uint2(pkf(vf.x, vf.y), pkf(vf.z, vf.w));
  }
}

__global__ void __launch_bounds__(256, 1)
fa_hmma7_kernel(const float* __restrict__ q, const float* __restrict__ k,
                const float* __restrict__ v, float* __restrict__ out) {
  const int t = threadIdx.x;
  const int w = t >> 5, lane = t & 31;
  const int g = lane >> 2, tt = lane & 3;
  const int qt = 15 - (int)blockIdx.x;     /* longest q-tiles first */
  const int h = blockIdx.y, b = blockIdx.z, hk = h >> 2;

  const float* qg = q + (size_t)(b * SEQ + qt * 128) * QROW + h * 128;
  const float* kg = k + (size_t)b * SEQ * KROW + hk * 128;
  const float* vg = v + (size_t)b * SEQ * KROW + hk * 128;

  /* ---- ones pad columns (V words 64..67 per row, both buffers), once ---- */
  {
    const int o1 = VOFF_W + (t >> 2) * 68 + 64 + (t & 3);
    smw[o1] = ONES2;
    smw[BUFW + o1] = ONES2;
  }

  /* ---- stage Q (scaled fp16) into buffer 0 area [m][68w], m=0..127 ---- */
#pragma unroll
  for (int it = 0; it < 16; ++it) {
    const int idx = t + 256 * it, m = idx >> 5, d0 = (idx & 31) << 2;
    float4 qv = *(const float4*)(qg + (size_t)m * QROW + d0);
    *(uint2*)(smw + m * 68 + (d0 >> 1)) =
        make_uint2(pkf(qv.x * QSC, qv.y * QSC), pkf(qv.z * QSC, qv.w * QSC));
  }
  __syncthreads();

  /* lane offsets (words) for ldmatrix tile rows */
  const uint32_t sbase = smem_u32(smw);
  const int l = lane;
  const uint32_t LQ = (((l >> 3) & 1) * 8 + (l & 7)) * 68 + (l >> 4) * 4;  /* A & V-trans */
  const uint32_t LK = ((l >> 4) * 8 + (l & 7)) * 68 + ((l >> 3) & 1) * 4;  /* K non-trans */
  const uint32_t LO = (((l >> 3) & 1) * 8 + (l & 7)) * 68 + 64;            /* ones x2 */

  /* ---- Q A-fragments: 8 ldmatrix.x4 ---- */
  uint32_t qh[8][4];
  {
    const uint32_t qa = sbase + (16 * w * 68 + LQ) * 4;
#pragma unroll
    for (int ks = 0; ks < 8; ++ks) {
      uint4 A = ldsm4(qa + ks * 32);
      qh[ks][0] = A.x; qh[ks][1] = A.y; qh[ks][2] = A.z; qh[ks][3] = A.w;
    }
  }
  __syncthreads();

  fill_kv(smw, kg, vg, t);   /* prefill buffer 0 with kv-tile 0 */

  float o[16][4];
#pragma unroll
  for (int nt = 0; nt < 16; ++nt)
#pragma unroll
    for (int i = 0; i < 4; ++i) o[nt][i] = 0.0f;
  float lf[4] = {0.f, 0.f, 0.f, 0.f};

  const int r0 = qt * 128 + 16 * w + g;     /* thread rows r0, r0+8 */
  const int rmax = qt * 128 + 16 * w + 15;
  const int nkt = 2 * qt + 2;

  for (int kt = 0; kt < nkt; ++kt) {
    __syncthreads();  /* fill(kt) visible; prior reads of that buffer done */
    const uint32_t bwa = sbase + ((kt & 1) * BUFW) * 4;
    const bool active = (kt * 64 <= rmax);

    float s[8][4];
    if (active) {
      /* ---- S = Q K^T - PBIAS ; B-frags via ldmatrix.x4 (2 nt per load) ---- */
#pragma unroll
      for (int nt = 0; nt < 8; ++nt)
#pragma unroll
        for (int i = 0; i < 4; ++i) s[nt][i] = -PBIAS;
      const uint32_t kbase = bwa + LK * 4;
#pragma unroll
      for (int ks = 0; ks < 8; ++ks) {
#pragma unroll
        for (int ntp = 0; ntp < 4; ++ntp) {
          uint4 B = ldsm4(kbase + (ntp * 1088 + ks * 8) * 4);
          hmma(s[2 * ntp],     qh[ks], B.x, B.y);
          hmma(s[2 * ntp + 1], qh[ks], B.z, B.w);
        }
      }
    }

    /* ---- prefetch next kv-tile (overlaps softmax + PV) ---- */
    if (kt + 1 < nkt)
      fill_kv(smw + ((kt + 1) & 1) * BUFW,
              kg + (size_t)((kt + 1) * 64) * KROW,
              vg + (size_t)((kt + 1) * 64) * KROW, t);

    if (active) {
      /* ---- causal mask + exp2 ; P packed straight into A-fragments ---- */
      const bool needMask = (kt * 64 + 63 > qt * 128 + 16 * w);
      uint32_t pp[8][2];
#pragma unroll
      for (int nt = 0; nt < 8; ++nt) {
        if (needMask) {
          const int c = kt * 64 + nt * 8 + 2 * tt;
          if (c > r0)         s[nt][0] = -1e30f;
          if (c + 1 > r0)     s[nt][1] = -1e30f;
          if (c > r0 + 8)     s[nt][2] = -1e30f;
          if (c + 1 > r0 + 8) s[nt][3] = -1e30f;
        }
        pp[nt][0] = pkf(ex2f(s[nt][0]), ex2f(s[nt][1]));  /* row g   */
        pp[nt][1] = pkf(ex2f(s[nt][2]), ex2f(s[nt][3]));  /* row g+8 */
      }

      /* ---- O += P V ; l += P * ones ; B-frags via ldmatrix.trans ---- */
      const uint32_t vbase = bwa + (VOFF_W + LQ) * 4;
      const uint32_t obase = bwa + (VOFF_W + LO) * 4;
#pragma unroll
      for (int ks = 0; ks < 4; ++ks) {
        uint32_t ap[4];
        ap[0] = pp[2 * ks][0];
        ap[1] = pp[2 * ks][1];
        ap[2] = pp[2 * ks + 1][0];
        ap[3] = pp[2 * ks + 1][1];
#pragma unroll
        for (int ntp = 0; ntp < 8; ++ntp) {
          uint4 B = ldsm4t(vbase + (ks * 1088 + ntp * 8) * 4);
          hmma(o[2 * ntp],     ap, B.x, B.y);
          hmma(o[2 * ntp + 1], ap, B.z, B.w);
        }
        uint2 Bl = ldsm2t(obase + (ks * 1088) * 4);
        hmma(lf, ap, Bl.x, Bl.y);
      }
    }
  }

  /* ---- epilogue: O / l ---- */
  const float i0 = 1.0f / lf[0], i1 = 1.0f / lf[2];
  float* og = out + (size_t)(b * SEQ + r0) * QROW + h * 128 + 2 * tt;
#pragma unroll
  for (int nt = 0; nt < 16; ++nt) {
    *(float2*)(og + nt * 8) = make_float2(o[nt][0] * i0, o[nt][1] * i0);
    *(float2*)(og + 8 * QROW + nt * 8) = make_float2(o[nt][2] * i1, o[nt][3] * i1);
  }
}

extern "C" void kernel_launch(void* const* d_in, const int* in_sizes, int n_in,
                              void* d_out, int out_size) {
  const float* q = (const float*)d_in[0];
  const float* k = (const float*)d_in[1];
  const float* v = (const float*)d_in[2];
  float* out = (float*)d_out;
  (void)in_sizes; (void)n_in; (void)out_size;
  cudaFuncSetAttribute(fa_hmma7_kernel, cudaFuncAttributeMaxDynamicSharedMemorySize, SMEM_BYTES);
  fa_hmma7_kernel<<<dim3(16, 16, 4), 256, SMEM_BYTES>>>(q, k, v, out);
}